// round 13
// baseline (speedup 1.0000x reference)
#include <cuda_runtime.h>
#include <cuda_fp16.h>
#include <cstdint>

// Problem dims (fixed by the dataset)
#define B_   32
#define CIN  32
#define T_   12
#define N_   1024
#define KS   3
#define COUT 64
#define R_   (B_ * CIN * T_)   // 12288

#define RTILES (R_ / 16)       // 768
#define KTILES (N_ / 16)       // 64

// Scratch (__device__ globals; no allocations allowed)
__device__ __half g_xc [(size_t)KS * R_ * N_];     // 75.5 MB fp16
__device__ uint4  g_xfrag[(size_t)RTILES * KTILES * 32];  // 25.2 MB: A fragments
__device__ __half g_lhi[(size_t)KS * N_ * N_];     // fp16(Lk)
__device__ __half g_thH[64 * 104];                 // theta fp16, rows padded to 104

__device__ __forceinline__ uint32_t smem_u32(const void* p) {
    uint32_t a;
    asm("{ .reg .u64 t; cvta.to.shared.u64 t, %1; cvt.u32.u64 %0, t; }"
        : "=r"(a) : "l"(p));
    return a;
}
__device__ __forceinline__ void cp16(uint32_t dst, const void* src) {
    asm volatile("cp.async.cg.shared.global [%0], [%1], 16;" :: "r"(dst), "l"(src));
}
#define CP_COMMIT() asm volatile("cp.async.commit_group;" ::: "memory")
#define CP_WAIT(n)  asm volatile("cp.async.wait_group %0;" :: "n"(n) : "memory")

__device__ __forceinline__ void ldmx4(uint32_t* r, uint32_t addr) {
    asm volatile("ldmatrix.sync.aligned.m8n8.x4.shared.b16 {%0,%1,%2,%3}, [%4];"
                 : "=r"(r[0]), "=r"(r[1]), "=r"(r[2]), "=r"(r[3]) : "r"(addr));
}
__device__ __forceinline__ void ldmx4t(uint32_t* r, uint32_t addr) {
    asm volatile("ldmatrix.sync.aligned.m8n8.x4.trans.shared.b16 {%0,%1,%2,%3}, [%4];"
                 : "=r"(r[0]), "=r"(r[1]), "=r"(r[2]), "=r"(r[3]) : "r"(addr));
}

// D += A*B, m16n8k16, fp16 in / fp32 acc
#define MMA_F16(d, a, b0, b1)                                                 \
    asm volatile("mma.sync.aligned.m16n8k16.row.col.f32.f16.f16.f32 "         \
                 "{%0,%1,%2,%3}, {%4,%5,%6,%7}, {%8,%9}, {%0,%1,%2,%3};"      \
                 : "+f"((d)[0]), "+f"((d)[1]), "+f"((d)[2]), "+f"((d)[3])     \
                 : "r"((a)[0]), "r"((a)[1]), "r"((a)[2]), "r"((a)[3]),        \
                   "r"(b0), "r"(b1))

// ---------------------------------------------------------------------------
// prep kernels
// ---------------------------------------------------------------------------
__device__ __forceinline__ uint32_t pack2(float a, float b) {
    __half2 h = __floats2half2_rn(a, b);
    return *reinterpret_cast<uint32_t*>(&h);
}

// x fp32 -> A-fragment-layout fp16 (one 512B block per 16x16 tile, lane-major)
__global__ __launch_bounds__(256) void split_x(const float* __restrict__ src) {
    const int tile = blockIdx.x * 8 + (threadIdx.x >> 5);
    const int lane = threadIdx.x & 31;
    const int rT = tile >> 6, kT = tile & 63;
    const int r0 = rT * 16 + (lane >> 2);
    const int k0 = kT * 16 + (lane & 3) * 2;
    const float* p = src + (size_t)r0 * N_ + k0;
    float2 v00 = *(const float2*)p;
    float2 v10 = *(const float2*)(p + 8 * N_);
    float2 v01 = *(const float2*)(p + 8);
    float2 v11 = *(const float2*)(p + 8 * N_ + 8);
    uint4 o;
    o.x = pack2(v00.x, v00.y);
    o.y = pack2(v10.x, v10.y);
    o.z = pack2(v01.x, v01.y);
    o.w = pack2(v11.x, v11.y);
    g_xfrag[(size_t)tile * 32 + lane] = o;
}
__global__ __launch_bounds__(256) void split_l(const float* __restrict__ src) {
    size_t i = ((size_t)blockIdx.x * 256 + threadIdx.x) * 4;
    float4 v = *(const float4*)(src + i);
    *(__half2*)(g_lhi + i)     = __floats2half2_rn(v.x, v.y);
    *(__half2*)(g_lhi + i + 2) = __floats2half2_rn(v.z, v.w);
}
__global__ __launch_bounds__(256) void prep_theta(const float* __restrict__ theta) {
    int idx = blockIdx.x * 256 + threadIdx.x;
    int o = idx / 104, c = idx % 104;
    float v = 0.0f;
    if (c < 96) {
        int k = c >> 5, i = c & 31;
        v = theta[i * (COUT * KS) + o * KS + k];
    }
    g_thH[idx] = __float2half_rn(v);
}

// ---------------------------------------------------------------------------
// Stage 1: fp16 HMMA, 128x128 tile, KC=128 (8 chunks), B via smem 3-stage,
// A direct from g_xfrag via LDG.128, register double-buffered per k-step.
// 8 warps = 4 warp-rows(32) x 2 warp-cols(64); 2 CTAs/SM.
// ---------------------------------------------------------------------------
#define KC         128
#define ROW1       272                     // 128 halfs + 16B pad (=144 mod 128)
#define STG_STRIDE (128 * ROW1)            // 34816
#define NSTAGE     3
#define S1_SMEM    (NSTAGE * STG_STRIDE)   // 104448 B

__global__ __launch_bounds__(256, 2) void stage1_mma() {
    extern __shared__ char smem[];
    const uint32_t sb = smem_u32(smem);

    const int tid  = threadIdx.x;
    const int lane = tid & 31;
    const int wid  = tid >> 5;
    const int wr   = wid >> 1;    // warp row 0..3 (32 rows each)
    const int wc   = wid & 1;     // warp col 0..1 (64 cols each)
    const int gid  = lane >> 2;
    const int tig  = lane & 3;

    const int kz    = blockIdx.z;
    const int rBase = blockIdx.y * 128;
    const int nBase = blockIdx.x * 128;

    const __half* Bh = g_lhi + ((size_t)kz * N_ + nBase) * N_;

    // A fragment streams (one per mt), advancing 32 uint4 per 16-k step
    const uint4* aP0 = g_xfrag + ((size_t)(rBase / 16 + wr * 2 + 0) * KTILES) * 32 + lane;
    const uint4* aP1 = g_xfrag + ((size_t)(rBase / 16 + wr * 2 + 1) * KTILES) * 32 + lane;

    const uint32_t bRowOff = (uint32_t)((lane & 7) + ((lane >> 4) << 3)) * ROW1
                           + (uint32_t)((lane >> 3) & 1) * 16;
    const uint32_t bWarp = (uint32_t)(wc * 64) * ROW1;

    auto issue = [&](int c) {
        const uint32_t stg = sb + (uint32_t)(c % NSTAGE) * STG_STRIDE;
        const int kofs = c * KC;
        #pragma unroll
        for (int j = 0; j < 8; j++) {
            const int idx = j * 256 + tid;       // 0..2047: B 128 rows x 16 cp16
            int row = idx >> 4, c16 = idx & 15;
            cp16(stg + row * ROW1 + c16 * 16,
                 Bh + (size_t)row * N_ + kofs + c16 * 8);
        }
        CP_COMMIT();
    };

    float acc[2][8][4];
    #pragma unroll
    for (int mt = 0; mt < 2; mt++)
        #pragma unroll
        for (int nt = 0; nt < 8; nt++)
            #pragma unroll
            for (int q = 0; q < 4; q++) acc[mt][nt][q] = 0.0f;

    issue(0); issue(1);

    uint4 aCur0 = __ldg(aP0);
    uint4 aCur1 = __ldg(aP1);

    const int NCHUNK = N_ / KC;   // 8
    for (int c = 0; c < NCHUNK; c++) {
        if (c < NCHUNK - 1) CP_WAIT(1); else CP_WAIT(0);
        __syncthreads();
        if (c + 2 < NCHUNK) issue(c + 2);

        const uint32_t stg = sb + (uint32_t)(c % NSTAGE) * STG_STRIDE;
        const uint32_t sB  = stg + bWarp + bRowOff;

        #pragma unroll
        for (int kst = 0; kst < 8; kst++) {
            const int ks  = c * 8 + kst;
            const int nks = (ks + 1 < 8 * NCHUNK) ? ks + 1 : ks;
            // prefetch next k-step's A fragments (covered by this k-step's MMAs)
            uint4 aN0 = __ldg(aP0 + (size_t)nks * 32);
            uint4 aN1 = __ldg(aP1 + (size_t)nks * 32);

            const uint32_t kb = kst * 32;
            const uint32_t* a0 = reinterpret_cast<const uint32_t*>(&aCur0);
            const uint32_t* a1 = reinterpret_cast<const uint32_t*>(&aCur1);
            #pragma unroll
            for (int np = 0; np < 4; np++) {
                uint32_t bh[4];
                ldmx4(bh, sB + (uint32_t)np * (16 * ROW1) + kb);
                MMA_F16(acc[0][2 * np],     a0, bh[0], bh[1]);
                MMA_F16(acc[0][2 * np + 1], a0, bh[2], bh[3]);
                MMA_F16(acc[1][2 * np],     a1, bh[0], bh[1]);
                MMA_F16(acc[1][2 * np + 1], a1, bh[2], bh[3]);
            }
            aCur0 = aN0;
            aCur1 = aN1;
        }
    }

    __half* C = g_xc + (size_t)kz * R_ * N_;
    const int rw = rBase + wr * 32;
    const int cw = nBase + wc * 64;
    #pragma unroll
    for (int mt = 0; mt < 2; mt++) {
        #pragma unroll
        for (int nt = 0; nt < 8; nt++) {
            const int r0 = rw + mt * 16 + gid;
            const int c0 = cw + nt * 8 + tig * 2;
            __half2 v01 = __floats2half2_rn(acc[mt][nt][0], acc[mt][nt][1]);
            __half2 v23 = __floats2half2_rn(acc[mt][nt][2], acc[mt][nt][3]);
            *(__half2*)&C[(size_t)r0 * N_ + c0]       = v01;
            *(__half2*)&C[(size_t)(r0 + 8) * N_ + c0] = v23;
        }
    }
}

// ---------------------------------------------------------------------------
// Stage 2 (HMMA, single-pass theta): per (b,t,n-block 128):
// D[o=64][n=128] = sum_ik th[ik][o] * xc[ik][n]
// ---------------------------------------------------------------------------
#define XC_ROW   272
#define XC_SLAB  (32 * XC_ROW)              // 8704
#define TH_ROW   208
#define S2_TH    (3 * XC_SLAB)              // 26112
#define S2_SMEM  (S2_TH + 64 * TH_ROW)      // 39424

__global__ __launch_bounds__(256) void stage2_mma(
    const float* __restrict__ X,
    const float* __restrict__ bias,
    float* __restrict__ out)
{
    extern __shared__ char smem[];
    const uint32_t sb = smem_u32(smem);

    const int tid  = threadIdx.x;
    const int lane = tid & 31;
    const int wid  = tid >> 5;
    const int wr2  = wid >> 1;   // o-row 0..3 (16 each)
    const int wc2  = wid & 1;    // n-col 0..1 (64 each)
    const int gid  = lane >> 2;
    const int tig  = lane & 3;

    const int n0 = blockIdx.x * 128;
    const int t  = blockIdx.y;
    const int bb = blockIdx.z;

    // group 0: theta (832 cp16)
    for (int idx = tid; idx < 832; idx += 256) {
        int row = idx / 13, c16 = idx % 13;
        cp16(sb + S2_TH + row * TH_ROW + c16 * 16, g_thH + row * 104 + c16 * 8);
    }
    CP_COMMIT();

    // groups 1..3: xc slabs (512 cp16 each)
    #pragma unroll
    for (int c = 0; c < KS; c++) {
        const __half* src = g_xc + (size_t)c * R_ * N_;
        #pragma unroll
        for (int j = 0; j < 2; j++) {
            int idx = j * 256 + tid;
            int row = idx >> 4, c16 = idx & 15;
            cp16(sb + c * XC_SLAB + row * XC_ROW + c16 * 16,
                 src + ((size_t)(bb * CIN + row) * T_ + t) * N_ + n0 + c16 * 8);
        }
        CP_COMMIT();
    }

    const uint32_t aOff = (uint32_t)(lane & 15) * TH_ROW + (uint32_t)(lane >> 4) * 16
                        + (uint32_t)wr2 * (16 * TH_ROW);
    const uint32_t bOff = (uint32_t)(lane & 15) * XC_ROW + (uint32_t)(lane >> 4) * 16
                        + (uint32_t)wc2 * 128;

    float acc[8][4];
    #pragma unroll
    for (int nt = 0; nt < 8; nt++)
        #pragma unroll
        for (int q = 0; q < 4; q++) acc[nt][q] = 0.0f;

    #pragma unroll
    for (int c = 0; c < KS; c++) {
        if (c == 0)      CP_WAIT(2);
        else if (c == 1) CP_WAIT(1);
        else             CP_WAIT(0);
        __syncthreads();

        #pragma unroll
        for (int kst = 0; kst < 2; kst++) {
            const uint32_t ikByte = (uint32_t)(c * 32 + kst * 16) * 2;
            uint32_t ah[4];
            ldmx4(ah, sb + S2_TH + aOff + ikByte);
            #pragma unroll
            for (int np = 0; np < 4; np++) {
                uint32_t bx[4];
                ldmx4t(bx, sb + c * XC_SLAB + (uint32_t)kst * (16 * XC_ROW)
                           + bOff + np * 32);
                MMA_F16(acc[2 * np],     ah, bx[0], bx[1]);
                MMA_F16(acc[2 * np + 1], ah, bx[2], bx[3]);
            }
        }
    }

    // epilogue: bias + residual (o<32) + relu
    #pragma unroll
    for (int half = 0; half < 2; half++) {
        const int o = wr2 * 16 + half * 8 + gid;
        const float bo = __ldg(bias + o);
        const float* xr = (o < CIN)
            ? X + ((size_t)(bb * CIN + o) * T_ + t) * N_ + n0 : nullptr;
        float* orow = out + ((size_t)(bb * COUT + o) * T_ + t) * N_ + n0;
        #pragma unroll
        for (int nt = 0; nt < 8; nt++) {
            const int nn = wc2 * 64 + nt * 8 + tig * 2;
            float v0 = acc[nt][half * 2 + 0] + bo;
            float v1 = acc[nt][half * 2 + 1] + bo;
            if (xr) {
                float2 r = *(const float2*)(xr + nn);
                v0 += r.x; v1 += r.y;
            }
            *(float2*)(orow + nn) = make_float2(fmaxf(v0, 0.f), fmaxf(v1, 0.f));
        }
    }
}

extern "C" void kernel_launch(void* const* d_in, const int* in_sizes, int n_in,
                              void* d_out, int out_size)
{
    const float* x     = (const float*)d_in[0];
    const float* Lk    = (const float*)d_in[1];
    const float* theta = (const float*)d_in[2];
    const float* bias  = (const float*)d_in[3];
    float* out = (float*)d_out;

    static bool attr_done = false;
    if (!attr_done) {
        cudaFuncSetAttribute(stage1_mma,
                             cudaFuncAttributeMaxDynamicSharedMemorySize, S1_SMEM);
        cudaFuncSetAttribute(stage2_mma,
                             cudaFuncAttributeMaxDynamicSharedMemorySize, S2_SMEM);
        attr_done = true;
    }

    split_x<<<(RTILES * KTILES) / 8, 256>>>(x);
    split_l<<<(KS * N_ * N_) / (256 * 4), 256>>>(Lk);
    prep_theta<<<(64 * 104) / 256, 256>>>(theta);

    dim3 g1(N_ / 128, R_ / 128, KS);   // (8, 96, 3) = 2304 CTAs
    stage1_mma<<<g1, 256, S1_SMEM>>>();

    dim3 g2(N_ / 128, T_, B_);         // (8, 12, 32) = 3072 CTAs
    stage2_mma<<<g2, 256, S2_SMEM>>>(x, bias, out);
}

// round 14
// speedup vs baseline: 1.1058x; 1.1058x over previous
#include <cuda_runtime.h>
#include <cuda_fp16.h>
#include <cstdint>

// Problem dims (fixed by the dataset)
#define B_   32
#define CIN  32
#define T_   12
#define N_   1024
#define KS   3
#define COUT 64
#define R_   (B_ * CIN * T_)   // 12288

#define RTILES (R_ / 16)       // 768
#define KTILES (N_ / 16)       // 64

// Scratch (__device__ globals; no allocations allowed)
__device__ __half g_xc [(size_t)KS * R_ * N_];     // 75.5 MB fp16
__device__ uint4  g_xfrag[(size_t)RTILES * KTILES * 32];  // 25.2 MB: A fragments
__device__ __half g_lhi[(size_t)KS * N_ * N_];     // fp16(Lk)
__device__ __half g_thH[64 * 104];                 // theta fp16, rows padded to 104

__device__ __forceinline__ uint32_t smem_u32(const void* p) {
    uint32_t a;
    asm("{ .reg .u64 t; cvta.to.shared.u64 t, %1; cvt.u32.u64 %0, t; }"
        : "=r"(a) : "l"(p));
    return a;
}
__device__ __forceinline__ void cp16(uint32_t dst, const void* src) {
    asm volatile("cp.async.cg.shared.global [%0], [%1], 16;" :: "r"(dst), "l"(src));
}
#define CP_COMMIT() asm volatile("cp.async.commit_group;" ::: "memory")
#define CP_WAIT(n)  asm volatile("cp.async.wait_group %0;" :: "n"(n) : "memory")

__device__ __forceinline__ void ldmx4(uint32_t* r, uint32_t addr) {
    asm volatile("ldmatrix.sync.aligned.m8n8.x4.shared.b16 {%0,%1,%2,%3}, [%4];"
                 : "=r"(r[0]), "=r"(r[1]), "=r"(r[2]), "=r"(r[3]) : "r"(addr));
}
__device__ __forceinline__ void ldmx4t(uint32_t* r, uint32_t addr) {
    asm volatile("ldmatrix.sync.aligned.m8n8.x4.trans.shared.b16 {%0,%1,%2,%3}, [%4];"
                 : "=r"(r[0]), "=r"(r[1]), "=r"(r[2]), "=r"(r[3]) : "r"(addr));
}

// D += A*B, m16n8k16, fp16 in / fp32 acc
#define MMA_F16(d, a, b0, b1)                                                 \
    asm volatile("mma.sync.aligned.m16n8k16.row.col.f32.f16.f16.f32 "         \
                 "{%0,%1,%2,%3}, {%4,%5,%6,%7}, {%8,%9}, {%0,%1,%2,%3};"      \
                 : "+f"((d)[0]), "+f"((d)[1]), "+f"((d)[2]), "+f"((d)[3])     \
                 : "r"((a)[0]), "r"((a)[1]), "r"((a)[2]), "r"((a)[3]),        \
                   "r"(b0), "r"(b1))

// ---------------------------------------------------------------------------
// merged prep kernel (one launch): x->fragments, Lk->fp16, theta->fp16
// ---------------------------------------------------------------------------
__device__ __forceinline__ uint32_t pack2(float a, float b) {
    __half2 h = __floats2half2_rn(a, b);
    return *reinterpret_cast<uint32_t*>(&h);
}

#define PREP_XB   6144                      // split_x blocks
#define PREP_LB   3072                      // split_l blocks
#define PREP_TB   26                        // prep_theta blocks
#define PREP_GRID (PREP_XB + PREP_LB + PREP_TB)

__global__ __launch_bounds__(256) void prep_all(
    const float* __restrict__ x,
    const float* __restrict__ Lk,
    const float* __restrict__ theta)
{
    const int bx = blockIdx.x;
    if (bx < PREP_XB) {
        // x fp32 -> A-fragment fp16 (512B block per 16x16 tile, lane-major)
        const int tile = bx * 8 + (threadIdx.x >> 5);
        const int lane = threadIdx.x & 31;
        const int rT = tile >> 6, kT = tile & 63;
        const int r0 = rT * 16 + (lane >> 2);
        const int k0 = kT * 16 + (lane & 3) * 2;
        const float* p = x + (size_t)r0 * N_ + k0;
        float2 v00 = *(const float2*)p;
        float2 v10 = *(const float2*)(p + 8 * N_);
        float2 v01 = *(const float2*)(p + 8);
        float2 v11 = *(const float2*)(p + 8 * N_ + 8);
        uint4 o;
        o.x = pack2(v00.x, v00.y);
        o.y = pack2(v10.x, v10.y);
        o.z = pack2(v01.x, v01.y);
        o.w = pack2(v11.x, v11.y);
        g_xfrag[(size_t)tile * 32 + lane] = o;
    } else if (bx < PREP_XB + PREP_LB) {
        size_t i = ((size_t)(bx - PREP_XB) * 256 + threadIdx.x) * 4;
        float4 v = *(const float4*)(Lk + i);
        *(__half2*)(g_lhi + i)     = __floats2half2_rn(v.x, v.y);
        *(__half2*)(g_lhi + i + 2) = __floats2half2_rn(v.z, v.w);
    } else {
        int idx = (bx - PREP_XB - PREP_LB) * 256 + threadIdx.x;  // < 6656
        int o = idx / 104, c = idx % 104;
        float v = 0.0f;
        if (c < 96) {
            int k = c >> 5, i = c & 31;
            v = theta[i * (COUT * KS) + o * KS + k];
        }
        g_thH[idx] = __float2half_rn(v);
    }
}

// ---------------------------------------------------------------------------
// Stage 1: fp16 HMMA, 128x128 tile, KC=64, B via smem 4-stage cp.async
// (issue moved ABOVE wait/barrier), A direct from g_xfrag (LDG.128,
// register double-buffered). 8 warps = 4x(32) x 2x(64); 2 CTAs/SM.
// ---------------------------------------------------------------------------
#define KC         64
#define ROW1       144
#define STG_STRIDE 18432                    // B only: 128*144
#define NSTAGE     4
#define S1_SMEM    (NSTAGE * STG_STRIDE)    // 73728 B

__global__ __launch_bounds__(256, 2) void stage1_mma() {
    extern __shared__ char smem[];
    const uint32_t sb = smem_u32(smem);

    const int tid  = threadIdx.x;
    const int lane = tid & 31;
    const int wid  = tid >> 5;
    const int wr   = wid >> 1;    // warp row 0..3 (32 rows each)
    const int wc   = wid & 1;     // warp col 0..1 (64 cols each)
    const int gid  = lane >> 2;
    const int tig  = lane & 3;

    const int kz    = blockIdx.z;
    const int rBase = blockIdx.y * 128;
    const int nBase = blockIdx.x * 128;

    const __half* Bh = g_lhi + ((size_t)kz * N_ + nBase) * N_;

    // A fragment streams (one per mt), advancing 32 uint4 per 16-k step
    const uint4* aP0 = g_xfrag + ((size_t)(rBase / 16 + wr * 2 + 0) * KTILES) * 32 + lane;
    const uint4* aP1 = g_xfrag + ((size_t)(rBase / 16 + wr * 2 + 1) * KTILES) * 32 + lane;

    const uint32_t bRowOff = (uint32_t)((lane & 7) + ((lane >> 4) << 3)) * ROW1
                           + (uint32_t)((lane >> 3) & 1) * 16;
    const uint32_t bWarp = (uint32_t)(wc * 64) * ROW1;

    auto issue = [&](int c) {
        const uint32_t stg = sb + (uint32_t)(c % NSTAGE) * STG_STRIDE;
        const int kofs = c * KC;
        #pragma unroll
        for (int j = 0; j < 4; j++) {
            const int idx = j * 256 + tid;       // 0..1023: B 128 rows x 8 cp16
            int row = idx >> 3, c16 = idx & 7;
            cp16(stg + row * ROW1 + c16 * 16,
                 Bh + (size_t)row * N_ + kofs + c16 * 8);
        }
        CP_COMMIT();
    };

    float acc[2][8][4];
    #pragma unroll
    for (int mt = 0; mt < 2; mt++)
        #pragma unroll
        for (int nt = 0; nt < 8; nt++)
            #pragma unroll
            for (int q = 0; q < 4; q++) acc[mt][nt][q] = 0.0f;

    issue(0); issue(1);

    uint4 aCur0 = __ldg(aP0);
    uint4 aCur1 = __ldg(aP1);

    const int NCHUNK = N_ / KC;   // 16
    for (int c = 0; c < NCHUNK; c++) {
        // stage (c+2)%4 was drained at chunk c-2 and barrier-ordered at c-1:
        // safe to refill BEFORE this chunk's wait/barrier.
        if (c + 2 < NCHUNK) issue(c + 2);
        if (c < NCHUNK - 2)       CP_WAIT(2);
        else if (c == NCHUNK - 2) CP_WAIT(1);
        else                      CP_WAIT(0);
        __syncthreads();

        const uint32_t stg = sb + (uint32_t)(c % NSTAGE) * STG_STRIDE;
        const uint32_t sB  = stg + bWarp + bRowOff;

        #pragma unroll
        for (int kst = 0; kst < 4; kst++) {
            const int ks  = c * 4 + kst;
            const int nks = (ks + 1 < 4 * NCHUNK) ? ks + 1 : ks;
            // prefetch next k-step's A fragments (covered by this k-step's MMAs)
            uint4 aN0 = __ldg(aP0 + (size_t)nks * 32);
            uint4 aN1 = __ldg(aP1 + (size_t)nks * 32);

            const uint32_t kb = kst * 32;
            const uint32_t* a0 = reinterpret_cast<const uint32_t*>(&aCur0);
            const uint32_t* a1 = reinterpret_cast<const uint32_t*>(&aCur1);
            #pragma unroll
            for (int np = 0; np < 4; np++) {
                uint32_t bh[4];
                ldmx4(bh, sB + (uint32_t)np * (16 * ROW1) + kb);
                MMA_F16(acc[0][2 * np],     a0, bh[0], bh[1]);
                MMA_F16(acc[0][2 * np + 1], a0, bh[2], bh[3]);
                MMA_F16(acc[1][2 * np],     a1, bh[0], bh[1]);
                MMA_F16(acc[1][2 * np + 1], a1, bh[2], bh[3]);
            }
            aCur0 = aN0;
            aCur1 = aN1;
        }
    }

    __half* C = g_xc + (size_t)kz * R_ * N_;
    const int rw = rBase + wr * 32;
    const int cw = nBase + wc * 64;
    #pragma unroll
    for (int mt = 0; mt < 2; mt++) {
        #pragma unroll
        for (int nt = 0; nt < 8; nt++) {
            const int r0 = rw + mt * 16 + gid;
            const int c0 = cw + nt * 8 + tig * 2;
            __half2 v01 = __floats2half2_rn(acc[mt][nt][0], acc[mt][nt][1]);
            __half2 v23 = __floats2half2_rn(acc[mt][nt][2], acc[mt][nt][3]);
            *(__half2*)&C[(size_t)r0 * N_ + c0]       = v01;
            *(__half2*)&C[(size_t)(r0 + 8) * N_ + c0] = v23;
        }
    }
}

// ---------------------------------------------------------------------------
// Stage 2 (HMMA, single-pass theta): per (b,t,n-block 128):
// D[o=64][n=128] = sum_ik th[ik][o] * xc[ik][n]
// ---------------------------------------------------------------------------
#define XC_ROW   272                        // 128 halfs + 16B pad
#define XC_SLAB  (32 * XC_ROW)              // 8704
#define TH_ROW   208                        // 104 halfs
#define S2_TH    (3 * XC_SLAB)              // 26112
#define S2_SMEM  (S2_TH + 64 * TH_ROW)      // 39424

__global__ __launch_bounds__(256) void stage2_mma(
    const float* __restrict__ X,
    const float* __restrict__ bias,
    float* __restrict__ out)
{
    extern __shared__ char smem[];
    const uint32_t sb = smem_u32(smem);

    const int tid  = threadIdx.x;
    const int lane = tid & 31;
    const int wid  = tid >> 5;
    const int wr2  = wid >> 1;   // o-row 0..3 (16 each)
    const int wc2  = wid & 1;    // n-col 0..1 (64 each)
    const int gid  = lane >> 2;
    const int tig  = lane & 3;

    const int n0 = blockIdx.x * 128;
    const int t  = blockIdx.y;
    const int bb = blockIdx.z;

    // group 0: theta (832 cp16)
    for (int idx = tid; idx < 832; idx += 256) {
        int row = idx / 13, c16 = idx % 13;
        cp16(sb + S2_TH + row * TH_ROW + c16 * 16, g_thH + row * 104 + c16 * 8);
    }
    CP_COMMIT();

    // groups 1..3: xc slabs (512 cp16 each)
    #pragma unroll
    for (int c = 0; c < KS; c++) {
        const __half* src = g_xc + (size_t)c * R_ * N_;
        #pragma unroll
        for (int j = 0; j < 2; j++) {
            int idx = j * 256 + tid;
            int row = idx >> 4, c16 = idx & 15;
            cp16(sb + c * XC_SLAB + row * XC_ROW + c16 * 16,
                 src + ((size_t)(bb * CIN + row) * T_ + t) * N_ + n0 + c16 * 8);
        }
        CP_COMMIT();
    }

    const uint32_t aOff = (uint32_t)(lane & 15) * TH_ROW + (uint32_t)(lane >> 4) * 16
                        + (uint32_t)wr2 * (16 * TH_ROW);
    const uint32_t bOff = (uint32_t)(lane & 15) * XC_ROW + (uint32_t)(lane >> 4) * 16
                        + (uint32_t)wc2 * 128;

    float acc[8][4];
    #pragma unroll
    for (int nt = 0; nt < 8; nt++)
        #pragma unroll
        for (int q = 0; q < 4; q++) acc[nt][q] = 0.0f;

    #pragma unroll
    for (int c = 0; c < KS; c++) {
        if (c == 0)      CP_WAIT(2);
        else if (c == 1) CP_WAIT(1);
        else             CP_WAIT(0);
        __syncthreads();

        #pragma unroll
        for (int kst = 0; kst < 2; kst++) {
            const uint32_t ikByte = (uint32_t)(c * 32 + kst * 16) * 2;
            uint32_t ah[4];
            ldmx4(ah, sb + S2_TH + aOff + ikByte);
            #pragma unroll
            for (int np = 0; np < 4; np++) {
                uint32_t bx[4];
                ldmx4t(bx, sb + c * XC_SLAB + (uint32_t)kst * (16 * XC_ROW)
                           + bOff + np * 32);
                MMA_F16(acc[2 * np],     ah, bx[0], bx[1]);
                MMA_F16(acc[2 * np + 1], ah, bx[2], bx[3]);
            }
        }
    }

    // epilogue: bias + residual (o<32) + relu
    #pragma unroll
    for (int half = 0; half < 2; half++) {
        const int o = wr2 * 16 + half * 8 + gid;
        const float bo = __ldg(bias + o);
        const float* xr = (o < CIN)
            ? X + ((size_t)(bb * CIN + o) * T_ + t) * N_ + n0 : nullptr;
        float* orow = out + ((size_t)(bb * COUT + o) * T_ + t) * N_ + n0;
        #pragma unroll
        for (int nt = 0; nt < 8; nt++) {
            const int nn = wc2 * 64 + nt * 8 + tig * 2;
            float v0 = acc[nt][half * 2 + 0] + bo;
            float v1 = acc[nt][half * 2 + 1] + bo;
            if (xr) {
                float2 r = *(const float2*)(xr + nn);
                v0 += r.x; v1 += r.y;
            }
            *(float2*)(orow + nn) = make_float2(fmaxf(v0, 0.f), fmaxf(v1, 0.f));
        }
    }
}

extern "C" void kernel_launch(void* const* d_in, const int* in_sizes, int n_in,
                              void* d_out, int out_size)
{
    const float* x     = (const float*)d_in[0];
    const float* Lk    = (const float*)d_in[1];
    const float* theta = (const float*)d_in[2];
    const float* bias  = (const float*)d_in[3];
    float* out = (float*)d_out;

    static bool attr_done = false;
    if (!attr_done) {
        cudaFuncSetAttribute(stage1_mma,
                             cudaFuncAttributeMaxDynamicSharedMemorySize, S1_SMEM);
        cudaFuncSetAttribute(stage2_mma,
                             cudaFuncAttributeMaxDynamicSharedMemorySize, S2_SMEM);
        attr_done = true;
    }

    prep_all<<<PREP_GRID, 256>>>(x, Lk, theta);

    dim3 g1(N_ / 128, R_ / 128, KS);   // (8, 96, 3) = 2304 CTAs
    stage1_mma<<<g1, 256, S1_SMEM>>>();

    dim3 g2(N_ / 128, T_, B_);         // (8, 12, 32) = 3072 CTAs
    stage2_mma<<<g2, 256, S2_SMEM>>>(x, bias, out);
}